// round 1
// baseline (speedup 1.0000x reference)
#include <cuda_runtime.h>
#include <math.h>

#define BATCH 4
#define SEQL 2048
#define DMODEL 2048
#define NHEADS 16
#define DKH 128
#define MROWS (BATCH*SEQL)   // 8192

// ---------------- scratch (static device globals; no allocs allowed) ----------------
static __device__ float g_Q[BATCH*NHEADS*SEQL*DKH];     // 64 MB, [B,H,S,dk]
static __device__ float g_K[BATCH*NHEADS*SEQL*DKH];     // 64 MB
static __device__ float g_V[BATCH*NHEADS*SEQL*DKH];     // 64 MB
static __device__ float g_ctx[BATCH*SEQL*DMODEL];       // 64 MB, [B,S,D]
static __device__ float g_cos[SEQL*(DKH/2)];            // RoPE tables
static __device__ float g_sin[SEQL*(DKH/2)];

// ---------------- RoPE table init (graph-capturable, deterministic) ----------------
__global__ void init_tables_kernel()
{
    int t = blockIdx.x;          // position 0..2047
    int i = threadIdx.x;         // pair index 0..63
    double freq = exp(-(double)i * (log(10000.0) / 64.0));
    float ang = (float)t * (float)freq;      // fp32 product, matching jnp.outer in fp32
    g_cos[t*64 + i] = (float)cos((double)ang);
    g_sin[t*64 + i] = (float)sin((double)ang);
}

// ---------------- tiled fp32 GEMM: C = A @ B^T (both K-major row-major) ----------------
// mode 0: A := g_ctx, write C row-major [8192,2048]        (output projection)
// mode 1: A := Ap(x), RoPE + 1/sqrt(dk) scale, write g_Q [B,H,S,dk]
// mode 2: A := Ap(x), RoPE,                    write g_K [B,H,S,dk]
// mode 3: A := Ap(x), plain,                   write g_V [B,H,S,dk]
#define BM 128
#define BN 128
#define BKC 16
#define TM 8
#define TN 8

__global__ void __launch_bounds__(256, 2) gemm_kernel(
    const float* __restrict__ Ap, const float* __restrict__ Bp,
    float* __restrict__ Cp, int mode, const int* __restrict__ tokpos)
{
    __shared__ float As[BKC][BM+4];
    __shared__ float Bs[BKC][BN+4];

    const float* A = (mode == 0) ? g_ctx : Ap;
    const int bm = blockIdx.y * BM;
    const int bn = blockIdx.x * BN;
    const int tid = threadIdx.x;
    const int tm = (tid >> 4) * TM;        // 0..120
    const int tn = (tid & 15) * TN;        // 0..120
    const int lr = tid >> 1;               // loader row 0..127
    const int lc = (tid & 1) * 8;          // loader col 0 or 8

    const float* Arow = A  + (size_t)(bm + lr) * DMODEL + lc;
    const float* Brow = Bp + (size_t)(bn + lr) * DMODEL + lc;

    float acc[TM][TN];
    #pragma unroll
    for (int i = 0; i < TM; i++)
        #pragma unroll
        for (int j = 0; j < TN; j++) acc[i][j] = 0.f;

    for (int k0 = 0; k0 < DMODEL; k0 += BKC) {
        float4 a0 = *(const float4*)(Arow + k0);
        float4 a1 = *(const float4*)(Arow + k0 + 4);
        float4 b0 = *(const float4*)(Brow + k0);
        float4 b1 = *(const float4*)(Brow + k0 + 4);
        __syncthreads();
        As[lc+0][lr]=a0.x; As[lc+1][lr]=a0.y; As[lc+2][lr]=a0.z; As[lc+3][lr]=a0.w;
        As[lc+4][lr]=a1.x; As[lc+5][lr]=a1.y; As[lc+6][lr]=a1.z; As[lc+7][lr]=a1.w;
        Bs[lc+0][lr]=b0.x; Bs[lc+1][lr]=b0.y; Bs[lc+2][lr]=b0.z; Bs[lc+3][lr]=b0.w;
        Bs[lc+4][lr]=b1.x; Bs[lc+5][lr]=b1.y; Bs[lc+6][lr]=b1.z; Bs[lc+7][lr]=b1.w;
        __syncthreads();
        #pragma unroll
        for (int kk = 0; kk < BKC; kk++) {
            float af[TM], bf[TN];
            *(float4*)&af[0] = *(const float4*)&As[kk][tm];
            *(float4*)&af[4] = *(const float4*)&As[kk][tm+4];
            *(float4*)&bf[0] = *(const float4*)&Bs[kk][tn];
            *(float4*)&bf[4] = *(const float4*)&Bs[kk][tn+4];
            #pragma unroll
            for (int i = 0; i < TM; i++)
                #pragma unroll
                for (int j = 0; j < TN; j++)
                    acc[i][j] += af[i] * bf[j];
        }
    }

    if (mode == 0) {
        #pragma unroll
        for (int i = 0; i < TM; i++) {
            float* crow = Cp + (size_t)(bm + tm + i) * DMODEL + bn + tn;
            *(float4*)&crow[0] = *(float4*)&acc[i][0];
            *(float4*)&crow[4] = *(float4*)&acc[i][4];
        }
    } else {
        const float qscale = 0.08838834764831845f;   // 1/sqrt(128)
        float* base = (mode == 1) ? g_Q : ((mode == 2) ? g_K : g_V);
        const int n0 = bn + tn;
        const int h  = n0 >> 7;      // head (8 cols stay inside one head)
        const int d0 = n0 & 127;     // dim within head (multiple of 8)
        #pragma unroll
        for (int i = 0; i < TM; i++) {
            int m = bm + tm + i;
            int b = m >> 11;
            int s = m & (SEQL - 1);
            float* dst = base + ((size_t)(b * NHEADS + h) * SEQL + s) * DKH + d0;
            if (mode == 3) {
                *(float4*)&dst[0] = *(float4*)&acc[i][0];
                *(float4*)&dst[4] = *(float4*)&acc[i][4];
            } else {
                int p = tokpos[s];
                float r[8];
                #pragma unroll
                for (int jj = 0; jj < 4; jj++) {
                    int pi = (d0 >> 1) + jj;
                    float c  = g_cos[p*64 + pi];
                    float sn = g_sin[p*64 + pi];
                    float x1 = acc[i][2*jj];
                    float x2 = acc[i][2*jj+1];
                    r[2*jj]   = c*x1 - sn*x2;
                    r[2*jj+1] = sn*x1 + c*x2;
                }
                if (mode == 1) {
                    #pragma unroll
                    for (int u = 0; u < 8; u++) r[u] *= qscale;
                }
                *(float4*)&dst[0] = *(float4*)&r[0];
                *(float4*)&dst[4] = *(float4*)&r[4];
            }
        }
    }
}

// ---------------- causal flash attention, fp32 ----------------
// grid: (32 q-tiles of 64, 64 batch*head), 256 threads.
// smem: Qs[64][132] | KV union (Kts[128][64] then Vs[64][132]) | Ss[64][68] | rowscale[64] | rowl[64]
#define AQ 64
#define AKT 64
#define QSTR 132
#define SSTR 68
#define ATTN_SMEM_FLOATS (64*QSTR + 64*QSTR + 64*SSTR + 128)
#define ATTN_SMEM_BYTES (ATTN_SMEM_FLOATS*4)

__global__ void __launch_bounds__(256, 2) attn_kernel()
{
    extern __shared__ float sm[];
    float* Qs = sm;
    float* KV = Qs + 64*QSTR;
    float* Ss = KV + 64*QSTR;
    float* rowscale = Ss + 64*SSTR;
    float* rowl = rowscale + 64;

    const int qi = blockIdx.x;     // q tile 0..31
    const int bh = blockIdx.y;     // 0..63
    const int q0 = qi * AQ;
    const int tid = threadIdx.x;
    const float* Qb = g_Q + (size_t)bh * SEQL * DKH;
    const float* Kb = g_K + (size_t)bh * SEQL * DKH;
    const float* Vb = g_V + (size_t)bh * SEQL * DKH;

    const int lrr = tid >> 2;            // 0..63 (tile row for loads)
    const int lcc = (tid & 3) * 32;      // col chunk

    {   // load Q tile once
        const float* src = Qb + (size_t)(q0 + lrr) * DKH + lcc;
        float* dstr = Qs + lrr * QSTR + lcc;
        #pragma unroll
        for (int u = 0; u < 8; u++) *(float4*)(dstr + 4*u) = *(const float4*)(src + 4*u);
    }

    float mcur = -INFINITY, lcur = 0.f;  // softmax stats (threads 0..63 own row tid)
    const int r0 = (tid >> 3) * 2;       // 2 rows per thread
    const int tx = tid & 7;
    const int cS = tx * 8;               // 8 score cols
    const int cV = tx * 16;              // 16 output cols
    float oacc[2][16];
    #pragma unroll
    for (int i = 0; i < 2; i++)
        #pragma unroll
        for (int j = 0; j < 16; j++) oacc[i][j] = 0.f;

    __syncthreads();

    for (int kt = 0; kt <= qi; kt++) {
        const int k0 = kt * AKT;

        float4 kreg[8];
        {
            const float* ksrc = Kb + (size_t)(k0 + lrr) * DKH + lcc;
            #pragma unroll
            for (int u = 0; u < 8; u++) kreg[u] = *(const float4*)(ksrc + 4*u);
        }
        __syncthreads();              // prior iteration's PV reads of KV/Ss are done
        #pragma unroll
        for (int u = 0; u < 8; u++) { // transposed store: Kts[d][r], stride 64
            int d = lcc + 4*u;
            KV[(d+0)*64 + lrr] = kreg[u].x;
            KV[(d+1)*64 + lrr] = kreg[u].y;
            KV[(d+2)*64 + lrr] = kreg[u].z;
            KV[(d+3)*64 + lrr] = kreg[u].w;
        }
        __syncthreads();

        // S = Q K^T (Q pre-scaled by 1/sqrt(dk))
        float sacc[2][8];
        #pragma unroll
        for (int i = 0; i < 2; i++)
            #pragma unroll
            for (int j = 0; j < 8; j++) sacc[i][j] = 0.f;
        #pragma unroll 4
        for (int k = 0; k < DKH; k++) {
            float a0 = Qs[(r0+0)*QSTR + k];
            float a1 = Qs[(r0+1)*QSTR + k];
            float bf[8];
            *(float4*)&bf[0] = *(const float4*)&KV[k*64 + cS];
            *(float4*)&bf[4] = *(const float4*)&KV[k*64 + cS + 4];
            #pragma unroll
            for (int j = 0; j < 8; j++) { sacc[0][j] += a0*bf[j]; sacc[1][j] += a1*bf[j]; }
        }
        const bool diag = (kt == qi);
        #pragma unroll
        for (int i = 0; i < 2; i++) {
            int rg = q0 + r0 + i;
            #pragma unroll
            for (int j = 0; j < 8; j++) {
                float v = sacc[i][j];
                int cg = k0 + cS + j;
                if (diag && cg > rg) v = -1e30f;
                Ss[(r0+i)*SSTR + cS + j] = v;
            }
        }

        float4 vreg[8];
        {
            const float* vsrc = Vb + (size_t)(k0 + lrr) * DKH + lcc;
            #pragma unroll
            for (int u = 0; u < 8; u++) vreg[u] = *(const float4*)(vsrc + 4*u);
        }
        __syncthreads();              // Ss visible; Kts reads done -> safe to overwrite KV
        {
            float* vdst = KV + lrr * QSTR + lcc;   // Vs[r][d], stride 132
            #pragma unroll
            for (int u = 0; u < 8; u++) *(float4*)(vdst + 4*u) = vreg[u];
        }
        if (tid < 64) {               // online softmax, one row per thread
            float* srow = Ss + tid * SSTR;
            float mt = -INFINITY;
            #pragma unroll 8
            for (int j = 0; j < AKT; j++) mt = fmaxf(mt, srow[j]);
            float mnew = fmaxf(mcur, mt);
            float sc = expf(mcur - mnew);
            float ssum = 0.f;
            #pragma unroll 8
            for (int j = 0; j < AKT; j++) {
                float e = expf(srow[j] - mnew);
                srow[j] = e;
                ssum += e;
            }
            lcur = lcur * sc + ssum;
            mcur = mnew;
            rowscale[tid] = sc;
        }
        __syncthreads();

        {   // O = O*scale + P V
            float sc0 = rowscale[r0+0];
            float sc1 = rowscale[r0+1];
            #pragma unroll
            for (int j = 0; j < 16; j++) { oacc[0][j] *= sc0; oacc[1][j] *= sc1; }
            #pragma unroll 2
            for (int kk = 0; kk < AKT; kk++) {
                float p0 = Ss[(r0+0)*SSTR + kk];
                float p1 = Ss[(r0+1)*SSTR + kk];
                float vf[16];
                *(float4*)&vf[0]  = *(const float4*)&KV[kk*QSTR + cV];
                *(float4*)&vf[4]  = *(const float4*)&KV[kk*QSTR + cV + 4];
                *(float4*)&vf[8]  = *(const float4*)&KV[kk*QSTR + cV + 8];
                *(float4*)&vf[12] = *(const float4*)&KV[kk*QSTR + cV + 12];
                #pragma unroll
                for (int j = 0; j < 16; j++) { oacc[0][j] += p0*vf[j]; oacc[1][j] += p1*vf[j]; }
            }
        }
    }

    if (tid < 64) rowl[tid] = lcur;
    __syncthreads();

    const int b = bh >> 4, h = bh & 15;
    #pragma unroll
    for (int i = 0; i < 2; i++) {
        float inv = 1.0f / rowl[r0 + i];
        int s = q0 + r0 + i;
        float* dst = g_ctx + (size_t)b * SEQL * DMODEL + (size_t)s * DMODEL + h * DKH + cV;
        float r[16];
        #pragma unroll
        for (int j = 0; j < 16; j++) r[j] = oacc[i][j] * inv;
        *(float4*)&dst[0]  = *(float4*)&r[0];
        *(float4*)&dst[4]  = *(float4*)&r[4];
        *(float4*)&dst[8]  = *(float4*)&r[8];
        *(float4*)&dst[12] = *(float4*)&r[12];
    }
}

// ---------------- launch ----------------
extern "C" void kernel_launch(void* const* d_in, const int* in_sizes, int n_in,
                              void* d_out, int out_size)
{
    (void)in_sizes; (void)n_in; (void)out_size;
    const float* x      = (const float*)d_in[0];
    const int*   tokpos = (const int*)d_in[1];
    const float* Wq     = (const float*)d_in[2];
    const float* Wk     = (const float*)d_in[3];
    const float* Wv     = (const float*)d_in[4];
    const float* Wo     = (const float*)d_in[5];
    float* out = (float*)d_out;

    init_tables_kernel<<<SEQL, 64>>>();

    dim3 gg(DMODEL / BN, MROWS / BM);
    gemm_kernel<<<gg, 256>>>(x, Wq, nullptr, 1, tokpos);   // Q (+RoPE, +scale)
    gemm_kernel<<<gg, 256>>>(x, Wk, nullptr, 2, tokpos);   // K (+RoPE)
    gemm_kernel<<<gg, 256>>>(x, Wv, nullptr, 3, tokpos);   // V

    cudaFuncSetAttribute(attn_kernel, cudaFuncAttributeMaxDynamicSharedMemorySize, ATTN_SMEM_BYTES);
    attn_kernel<<<dim3(32, 64), 256, ATTN_SMEM_BYTES>>>();

    gemm_kernel<<<gg, 256>>>(nullptr, Wo, out, 0, nullptr); // output projection
}

// round 4
// speedup vs baseline: 1.3809x; 1.3809x over previous
#include <cuda_runtime.h>
#include <cuda_bf16.h>
#include <math.h>
#include <stdint.h>

#define BATCH 4
#define SEQL 2048
#define DMODEL 2048
#define NHEADS 16
#define DKH 128
#define MROWS (BATCH*SEQL)   // 8192

// ---------------- scratch (static device globals; no allocs allowed) ----------------
static __device__ float g_Q[BATCH*NHEADS*SEQL*DKH];     // [B,H,S,dk] fp32
static __device__ float g_K[BATCH*NHEADS*SEQL*DKH];
static __device__ float g_V[BATCH*NHEADS*SEQL*DKH];
static __device__ float g_ctx[BATCH*SEQL*DMODEL];       // attention output fp32
static __device__ float g_cos[SEQL*(DKH/2)];
static __device__ float g_sin[SEQL*(DKH/2)];
// hi/lo bf16 split operands (x and ctx share g_xhi/g_xlo: x is dead after QKV)
static __device__ __nv_bfloat16 g_xhi[MROWS*DMODEL];
static __device__ __nv_bfloat16 g_xlo[MROWS*DMODEL];
static __device__ __nv_bfloat16 g_wqhi[DMODEL*DMODEL];
static __device__ __nv_bfloat16 g_wqlo[DMODEL*DMODEL];
static __device__ __nv_bfloat16 g_wkhi[DMODEL*DMODEL];
static __device__ __nv_bfloat16 g_wklo[DMODEL*DMODEL];
static __device__ __nv_bfloat16 g_wvhi[DMODEL*DMODEL];
static __device__ __nv_bfloat16 g_wvlo[DMODEL*DMODEL];
static __device__ __nv_bfloat16 g_wohi[DMODEL*DMODEL];
static __device__ __nv_bfloat16 g_wolo[DMODEL*DMODEL];

// ---------------- small helpers ----------------
__device__ __forceinline__ uint32_t smem_u32(const void* p) {
    uint32_t a;
    asm("{ .reg .u64 t; cvta.to.shared.u64 t, %1; cvt.u32.u64 %0, t; }" : "=r"(a) : "l"(p));
    return a;
}
__device__ __forceinline__ void ldsm_x4(uint32_t* r, uint32_t addr) {
    asm volatile("ldmatrix.sync.aligned.m8n8.x4.shared.b16 {%0,%1,%2,%3}, [%4];"
        : "=r"(r[0]), "=r"(r[1]), "=r"(r[2]), "=r"(r[3]) : "r"(addr));
}
__device__ __forceinline__ void ldsm_x2(uint32_t* r, uint32_t addr) {
    asm volatile("ldmatrix.sync.aligned.m8n8.x2.shared.b16 {%0,%1}, [%2];"
        : "=r"(r[0]), "=r"(r[1]) : "r"(addr));
}
__device__ __forceinline__ void mma16816(float* d, const uint32_t* a, const uint32_t* b) {
    asm volatile("mma.sync.aligned.m16n8k16.row.col.f32.bf16.bf16.f32 "
        "{%0,%1,%2,%3}, {%4,%5,%6,%7}, {%8,%9}, {%0,%1,%2,%3};"
        : "+f"(d[0]), "+f"(d[1]), "+f"(d[2]), "+f"(d[3])
        : "r"(a[0]), "r"(a[1]), "r"(a[2]), "r"(a[3]), "r"(b[0]), "r"(b[1]));
}

// ---------------- RoPE table init ----------------
__global__ void init_tables_kernel()
{
    int t = blockIdx.x;
    int i = threadIdx.x;
    double freq = exp(-(double)i * (log(10000.0) / 64.0));
    float ang = (float)t * (float)freq;
    g_cos[t*64 + i] = (float)cos((double)ang);
    g_sin[t*64 + i] = (float)sin((double)ang);
}

// ---------------- fp32 -> (hi, lo) bf16 split ----------------
// which: 0=x->xhi/xlo, 1..4=W*, 5=g_ctx->xhi/xlo
__global__ void convert_hilo_kernel(const float* __restrict__ src, int which, int n4)
{
    int idx = blockIdx.x * blockDim.x + threadIdx.x;
    if (idx >= n4) return;
    const float* s = src ? src : g_ctx;
    __nv_bfloat16 *hi, *lo;
    switch (which) {
        case 1: hi = g_wqhi; lo = g_wqlo; break;
        case 2: hi = g_wkhi; lo = g_wklo; break;
        case 3: hi = g_wvhi; lo = g_wvlo; break;
        case 4: hi = g_wohi; lo = g_wolo; break;
        default: hi = g_xhi; lo = g_xlo; break;   // 0 and 5
    }
    float4 v = ((const float4*)s)[idx];
    __nv_bfloat16 h0 = __float2bfloat16(v.x);
    __nv_bfloat16 h1 = __float2bfloat16(v.y);
    __nv_bfloat16 h2 = __float2bfloat16(v.z);
    __nv_bfloat16 h3 = __float2bfloat16(v.w);
    __nv_bfloat16 l0 = __float2bfloat16(v.x - __bfloat162float(h0));
    __nv_bfloat16 l1 = __float2bfloat16(v.y - __bfloat162float(h1));
    __nv_bfloat16 l2 = __float2bfloat16(v.z - __bfloat162float(h2));
    __nv_bfloat16 l3 = __float2bfloat16(v.w - __bfloat162float(h3));
    __nv_bfloat162* hp = (__nv_bfloat162*)hi;
    __nv_bfloat162* lp = (__nv_bfloat162*)lo;
    hp[2*idx]   = __halves2bfloat162(h0, h1);
    hp[2*idx+1] = __halves2bfloat162(h2, h3);
    lp[2*idx]   = __halves2bfloat162(l0, l1);
    lp[2*idx+1] = __halves2bfloat162(l2, l3);
}

// ---------------- mma.sync bf16 hi/lo GEMM: C[m][n] = sum_k A[m][k]*B[n][k] ----------------
// 128x128 tile/CTA, 8 warps as 2(m)x4(n) -> 64x32 per warp.
// 3 passes (AhBh + AhBl + AlBh) into shared fp32 accumulators.
// mode 0: A=ctx(xhi/xlo), write Cp row-major
// mode 1/2: A=x, +RoPE (+1/sqrt(dk) for Q), write g_Q / g_K
// mode 3: A=x, plain, write g_V
#define KC 32
#define STR 40   // bf16 row stride (32 + 8 pad)

__global__ void __launch_bounds__(256, 2) ms_gemm_kernel(float* __restrict__ Cp, int mode,
                                                         const int* __restrict__ tokpos)
{
    __shared__ __nv_bfloat16 sAh[128*STR];
    __shared__ __nv_bfloat16 sAl[128*STR];
    __shared__ __nv_bfloat16 sBh[128*STR];
    __shared__ __nv_bfloat16 sBl[128*STR];

    const int tid = threadIdx.x;
    const int wid = tid >> 5, lane = tid & 31;
    const int wm = wid >> 2, wn = wid & 3;
    const int bm = blockIdx.y * 128, bn = blockIdx.x * 128;

    const __nv_bfloat16 *Ah = g_xhi, *Al = g_xlo, *Bh, *Bl;
    if (mode == 0)      { Bh = g_wohi; Bl = g_wolo; }
    else if (mode == 1) { Bh = g_wqhi; Bl = g_wqlo; }
    else if (mode == 2) { Bh = g_wkhi; Bl = g_wklo; }
    else                { Bh = g_wvhi; Bl = g_wvlo; }

    float acc[4][4][4];
    #pragma unroll
    for (int i = 0; i < 4; i++)
        #pragma unroll
        for (int j = 0; j < 4; j++)
            #pragma unroll
            for (int d = 0; d < 4; d++) acc[i][j][d] = 0.f;

    const uint32_t sah = smem_u32(sAh), sal = smem_u32(sAl);
    const uint32_t sbh = smem_u32(sBh), sbl = smem_u32(sBl);
    const int r8 = lane & 7, sel = lane >> 3;
    const int a_row_part = wm*64 + r8 + (sel & 1) * 8;    // + am*16
    const int a_col_part = (sel >> 1) * 8;                // + kof
    const int b_row_part = wn*32 + r8;                    // + an*8
    const int b_col_part = (sel & 1) * 8;                 // + kof (x2: lanes 0-15)

    for (int c = 0; c < 64; c++) {
        const int k0 = c * KC;
        __syncthreads();
        #pragma unroll
        for (int t = 0; t < 2; t++) {
            const int slot = tid + t*256;
            const int row = slot >> 2, seg = slot & 3;
            const int so = row*STR + seg*8;
            const size_t ga = (size_t)(bm + row) * DMODEL + k0 + seg*8;
            const size_t gb = (size_t)(bn + row) * DMODEL + k0 + seg*8;
            *(uint4*)(sAh + so) = *(const uint4*)(Ah + ga);
            *(uint4*)(sAl + so) = *(const uint4*)(Al + ga);
            *(uint4*)(sBh + so) = *(const uint4*)(Bh + gb);
            *(uint4*)(sBl + so) = *(const uint4*)(Bl + gb);
        }
        __syncthreads();
        #pragma unroll
        for (int kk = 0; kk < 2; kk++) {
            const int kof = kk * 16;
            uint32_t bfh[4][2], bfl[4][2];
            #pragma unroll
            for (int an = 0; an < 4; an++) {
                const uint32_t ba = 2u * (uint32_t)((b_row_part + an*8)*STR + b_col_part + kof);
                ldsm_x2(bfh[an], sbh + ba);
                ldsm_x2(bfl[an], sbl + ba);
            }
            #pragma unroll
            for (int am = 0; am < 4; am++) {
                const uint32_t aa = 2u * (uint32_t)((a_row_part + am*16)*STR + a_col_part + kof);
                uint32_t afh[4], afl[4];
                ldsm_x4(afh, sah + aa);
                ldsm_x4(afl, sal + aa);
                #pragma unroll
                for (int an = 0; an < 4; an++) {
                    mma16816(acc[am][an], afh, bfh[an]);
                    mma16816(acc[am][an], afh, bfl[an]);
                    mma16816(acc[am][an], afl, bfh[an]);
                }
            }
        }
    }

    // epilogue: thread owns rows (rr, rr+8), col pair (cc, cc+1) per atom
    const int rr = lane >> 2;
    const int cc = (lane & 3) * 2;
    if (mode == 0) {
        #pragma unroll
        for (int am = 0; am < 4; am++)
            #pragma unroll
            for (int h2 = 0; h2 < 2; h2++) {
                const int m = bm + wm*64 + am*16 + rr + h2*8;
                #pragma unroll
                for (int an = 0; an < 4; an++) {
                    const int n = bn + wn*32 + an*8 + cc;
                    float2 v2 = make_float2(acc[am][an][h2*2], acc[am][an][h2*2+1]);
                    *(float2*)(Cp + (size_t)m * DMODEL + n) = v2;
                }
            }
    } else {
        const int h = bn >> 7;
        float* base = (mode == 1) ? g_Q : ((mode == 2) ? g_K : g_V);
        const float qscale = 0.08838834764831845f;  // 1/sqrt(128)
        #pragma unroll
        for (int am = 0; am < 4; am++)
            #pragma unroll
            for (int h2 = 0; h2 < 2; h2++) {
                const int m = bm + wm*64 + am*16 + rr + h2*8;
                const int b = m >> 11;
                const int s = m & (SEQL - 1);
                float* drow = base + ((size_t)(b * NHEADS + h) * SEQL + s) * DKH;
                if (mode == 3) {
                    #pragma unroll
                    for (int an = 0; an < 4; an++) {
                        const int d = wn*32 + an*8 + cc;
                        float2 v2 = make_float2(acc[am][an][h2*2], acc[am][an][h2*2+1]);
                        *(float2*)(drow + d) = v2;
                    }
                } else {
                    const int p = tokpos[s];
                    #pragma unroll
                    for (int an = 0; an < 4; an++) {
                        const int d = wn*32 + an*8 + cc;
                        const int pi = d >> 1;
                        const float co = g_cos[p*64 + pi];
                        const float si = g_sin[p*64 + pi];
                        const float x1 = acc[am][an][h2*2];
                        const float x2 = acc[am][an][h2*2+1];
                        float r1 = co*x1 - si*x2;
                        float r2 = si*x1 + co*x2;
                        if (mode == 1) { r1 *= qscale; r2 *= qscale; }
                        *(float2*)(drow + d) = make_float2(r1, r2);
                    }
                }
            }
    }
}

// ---------------- causal flash attention, fp32 (R1-verified, unchanged) ----------------
#define AQ 64
#define AKT 64
#define QSTR 132
#define SSTR 68
#define ATTN_SMEM_FLOATS (64*QSTR + 64*QSTR + 64*SSTR + 128)
#define ATTN_SMEM_BYTES (ATTN_SMEM_FLOATS*4)

__global__ void __launch_bounds__(256, 2) attn_kernel()
{
    extern __shared__ float sm[];
    float* Qs = sm;
    float* KV = Qs + 64*QSTR;
    float* Ss = KV + 64*QSTR;
    float* rowscale = Ss + 64*SSTR;
    float* rowl = rowscale + 64;

    const int qi = blockIdx.x;
    const int bh = blockIdx.y;
    const int q0 = qi * AQ;
    const int tid = threadIdx.x;
    const float* Qb = g_Q + (size_t)bh * SEQL * DKH;
    const float* Kb = g_K + (size_t)bh * SEQL * DKH;
    const float* Vb = g_V + (size_t)bh * SEQL * DKH;

    const int lrr = tid >> 2;
    const int lcc = (tid & 3) * 32;

    {
        const float* src = Qb + (size_t)(q0 + lrr) * DKH + lcc;
        float* dstr = Qs + lrr * QSTR + lcc;
        #pragma unroll
        for (int u = 0; u < 8; u++) *(float4*)(dstr + 4*u) = *(const float4*)(src + 4*u);
    }

    float mcur = -INFINITY, lcur = 0.f;
    const int r0 = (tid >> 3) * 2;
    const int tx = tid & 7;
    const int cS = tx * 8;
    const int cV = tx * 16;
    float oacc[2][16];
    #pragma unroll
    for (int i = 0; i < 2; i++)
        #pragma unroll
        for (int j = 0; j < 16; j++) oacc[i][j] = 0.f;

    __syncthreads();

    for (int kt = 0; kt <= qi; kt++) {
        const int k0 = kt * AKT;

        float4 kreg[8];
        {
            const float* ksrc = Kb + (size_t)(k0 + lrr) * DKH + lcc;
            #pragma unroll
            for (int u = 0; u < 8; u++) kreg[u] = *(const float4*)(ksrc + 4*u);
        }
        __syncthreads();
        #pragma unroll
        for (int u = 0; u < 8; u++) {
            int d = lcc + 4*u;
            KV[(d+0)*64 + lrr] = kreg[u].x;
            KV[(d+1)*64 + lrr] = kreg[u].y;
            KV[(d+2)*64 + lrr] = kreg[u].z;
            KV[(d+3)*64 + lrr] = kreg[u].w;
        }
        __syncthreads();

        float sacc[2][8];
        #pragma unroll
        for (int i = 0; i < 2; i++)
            #pragma unroll
            for (int j = 0; j < 8; j++) sacc[i][j] = 0.f;
        #pragma unroll 4
        for (int k = 0; k < DKH; k++) {
            float a0 = Qs[(r0+0)*QSTR + k];
            float a1 = Qs[(r0+1)*QSTR + k];
            float bf[8];
            *(float4*)&bf[0] = *(const float4*)&KV[k*64 + cS];
            *(float4*)&bf[4] = *(const float4*)&KV[k*64 + cS + 4];
            #pragma unroll
            for (int j = 0; j < 8; j++) { sacc[0][j] += a0*bf[j]; sacc[1][j] += a1*bf[j]; }
        }
        const bool diag = (kt == qi);
        #pragma unroll
        for (int i = 0; i < 2; i++) {
            int rg = q0 + r0 + i;
            #pragma unroll
            for (int j = 0; j < 8; j++) {
                float vv = sacc[i][j];
                int cg = k0 + cS + j;
                if (diag && cg > rg) vv = -1e30f;
                Ss[(r0+i)*SSTR + cS + j] = vv;
            }
        }

        float4 vreg[8];
        {
            const float* vsrc = Vb + (size_t)(k0 + lrr) * DKH + lcc;
            #pragma unroll
            for (int u = 0; u < 8; u++) vreg[u] = *(const float4*)(vsrc + 4*u);
        }
        __syncthreads();
        {
            float* vdst = KV + lrr * QSTR + lcc;
            #pragma unroll
            for (int u = 0; u < 8; u++) *(float4*)(vdst + 4*u) = vreg[u];
        }
        if (tid < 64) {
            float* srow = Ss + tid * SSTR;
            float mt = -INFINITY;
            #pragma unroll 8
            for (int j = 0; j < AKT; j++) mt = fmaxf(mt, srow[j]);
            float mnew = fmaxf(mcur, mt);
            float sc = expf(mcur - mnew);
            float ssum = 0.f;
            #pragma unroll 8
            for (int j = 0; j < AKT; j++) {
                float e = expf(srow[j] - mnew);
                srow[j] = e;
                ssum += e;
            }
            lcur = lcur * sc + ssum;
            mcur = mnew;
            rowscale[tid] = sc;
        }
        __syncthreads();

        {
            float sc0 = rowscale[r0+0];
            float sc1 = rowscale[r0+1];
            #pragma unroll
            for (int j = 0; j < 16; j++) { oacc[0][j] *= sc0; oacc[1][j] *= sc1; }
            #pragma unroll 2
            for (int kk = 0; kk < AKT; kk++) {
                float p0 = Ss[(r0+0)*SSTR + kk];
                float p1 = Ss[(r0+1)*SSTR + kk];
                float vf[16];
                *(float4*)&vf[0]  = *(const float4*)&KV[kk*QSTR + cV];
                *(float4*)&vf[4]  = *(const float4*)&KV[kk*QSTR + cV + 4];
                *(float4*)&vf[8]  = *(const float4*)&KV[kk*QSTR + cV + 8];
                *(float4*)&vf[12] = *(const float4*)&KV[kk*QSTR + cV + 12];
                #pragma unroll
                for (int j = 0; j < 16; j++) { oacc[0][j] += p0*vf[j]; oacc[1][j] += p1*vf[j]; }
            }
        }
    }

    if (tid < 64) rowl[tid] = lcur;
    __syncthreads();

    const int b = bh >> 4, h = bh & 15;
    #pragma unroll
    for (int i = 0; i < 2; i++) {
        float inv = 1.0f / rowl[r0 + i];
        int s = q0 + r0 + i;
        float* dst = g_ctx + (size_t)b * SEQL * DMODEL + (size_t)s * DMODEL + h * DKH + cV;
        float r[16];
        #pragma unroll
        for (int j = 0; j < 16; j++) r[j] = oacc[i][j] * inv;
        *(float4*)&dst[0]  = *(float4*)&r[0];
        *(float4*)&dst[4]  = *(float4*)&r[4];
        *(float4*)&dst[8]  = *(float4*)&r[8];
        *(float4*)&dst[12] = *(float4*)&r[12];
    }
}

// ---------------- launch ----------------
extern "C" void kernel_launch(void* const* d_in, const int* in_sizes, int n_in,
                              void* d_out, int out_size)
{
    (void)in_sizes; (void)n_in; (void)out_size;
    const float* x      = (const float*)d_in[0];
    const int*   tokpos = (const int*)d_in[1];
    const float* Wq     = (const float*)d_in[2];
    const float* Wk     = (const float*)d_in[3];
    const float* Wv     = (const float*)d_in[4];
    const float* Wo     = (const float*)d_in[5];
    float* out = (float*)d_out;

    init_tables_kernel<<<SEQL, 64>>>();

    const int n4x = MROWS * DMODEL / 4;
    const int n4w = DMODEL * DMODEL / 4;
    convert_hilo_kernel<<<n4x/256, 256>>>(x,  0, n4x);
    convert_hilo_kernel<<<n4w/256, 256>>>(Wq, 1, n4w);
    convert_hilo_kernel<<<n4w/256, 256>>>(Wk, 2, n4w);
    convert_hilo_kernel<<<n4w/256, 256>>>(Wv, 3, n4w);
    convert_hilo_kernel<<<n4w/256, 256>>>(Wo, 4, n4w);

    dim3 gg(DMODEL / 128, MROWS / 128);
    ms_gemm_kernel<<<gg, 256>>>(nullptr, 1, tokpos);   // Q (+RoPE, +scale)
    ms_gemm_kernel<<<gg, 256>>>(nullptr, 2, tokpos);   // K (+RoPE)
    ms_gemm_kernel<<<gg, 256>>>(nullptr, 3, tokpos);   // V

    cudaFuncSetAttribute(attn_kernel, cudaFuncAttributeMaxDynamicSharedMemorySize, ATTN_SMEM_BYTES);
    attn_kernel<<<dim3(32, 64), 256, ATTN_SMEM_BYTES>>>();

    convert_hilo_kernel<<<n4x/256, 256>>>(nullptr, 5, n4x);  // ctx -> xhi/xlo
    ms_gemm_kernel<<<gg, 256>>>(out, 0, nullptr);            // output projection
}

// round 7
// speedup vs baseline: 3.6415x; 2.6370x over previous
#include <cuda_runtime.h>
#include <cuda_bf16.h>
#include <math.h>
#include <stdint.h>

#define BATCH 4
#define SEQL 2048
#define DMODEL 2048
#define NHEADS 16
#define DKH 128
#define MROWS (BATCH*SEQL)   // 8192

// ---------------- scratch (static device globals; no allocs allowed) ----------------
static __device__ float g_Q[BATCH*NHEADS*SEQL*DKH];     // [B,H,S,dk] fp32
static __device__ float g_K[BATCH*NHEADS*SEQL*DKH];
static __device__ float g_V[BATCH*NHEADS*SEQL*DKH];
static __device__ float g_ctx[BATCH*SEQL*DMODEL];       // attention output fp32
static __device__ float g_cos[SEQL*(DKH/2)];
static __device__ float g_sin[SEQL*(DKH/2)];
// hi/lo bf16 split operands (x and ctx share g_xhi/g_xlo: x dead after QKV)
static __device__ __nv_bfloat16 g_xhi[MROWS*DMODEL];
static __device__ __nv_bfloat16 g_xlo[MROWS*DMODEL];
static __device__ __nv_bfloat16 g_wqhi[DMODEL*DMODEL];
static __device__ __nv_bfloat16 g_wqlo[DMODEL*DMODEL];
static __device__ __nv_bfloat16 g_wkhi[DMODEL*DMODEL];
static __device__ __nv_bfloat16 g_wklo[DMODEL*DMODEL];
static __device__ __nv_bfloat16 g_wvhi[DMODEL*DMODEL];
static __device__ __nv_bfloat16 g_wvlo[DMODEL*DMODEL];
static __device__ __nv_bfloat16 g_wohi[DMODEL*DMODEL];
static __device__ __nv_bfloat16 g_wolo[DMODEL*DMODEL];

// ---------------- helpers ----------------
__device__ __forceinline__ uint32_t smem_u32(const void* p) {
    uint32_t a;
    asm("{ .reg .u64 t; cvta.to.shared.u64 t, %1; cvt.u32.u64 %0, t; }" : "=r"(a) : "l"(p));
    return a;
}
__device__ __forceinline__ void ldsm_x4(uint32_t* r, uint32_t addr) {
    asm volatile("ldmatrix.sync.aligned.m8n8.x4.shared.b16 {%0,%1,%2,%3}, [%4];"
        : "=r"(r[0]), "=r"(r[1]), "=r"(r[2]), "=r"(r[3]) : "r"(addr));
}
__device__ __forceinline__ void ldsm_x4_t(uint32_t* r, uint32_t addr) {
    asm volatile("ldmatrix.sync.aligned.m8n8.x4.trans.shared.b16 {%0,%1,%2,%3}, [%4];"
        : "=r"(r[0]), "=r"(r[1]), "=r"(r[2]), "=r"(r[3]) : "r"(addr));
}
__device__ __forceinline__ void ldsm_x2(uint32_t* r, uint32_t addr) {
    asm volatile("ldmatrix.sync.aligned.m8n8.x2.shared.b16 {%0,%1}, [%2];"
        : "=r"(r[0]), "=r"(r[1]) : "r"(addr));
}
__device__ __forceinline__ void mma16816(float* d, const uint32_t* a, const uint32_t* b) {
    asm volatile("mma.sync.aligned.m16n8k16.row.col.f32.bf16.bf16.f32 "
        "{%0,%1,%2,%3}, {%4,%5,%6,%7}, {%8,%9}, {%0,%1,%2,%3};"
        : "+f"(d[0]), "+f"(d[1]), "+f"(d[2]), "+f"(d[3])
        : "r"(a[0]), "r"(a[1]), "r"(a[2]), "r"(a[3]), "r"(b[0]), "r"(b[1]));
}
__device__ __forceinline__ uint32_t pack_hilo2(float x, float y,
                                               __nv_bfloat16& hx, __nv_bfloat16& hy) {
    hx = __float2bfloat16(x); hy = __float2bfloat16(y);
    __nv_bfloat162 p = __halves2bfloat162(hx, hy);
    return *(uint32_t*)&p;
}
// split 8 fp32 into packed bf16 hi (uint4) and lo (uint4)
__device__ __forceinline__ void split8(float4 a, float4 b, uint4& hi, uint4& lo) {
    float f[8] = {a.x, a.y, a.z, a.w, b.x, b.y, b.z, b.w};
    uint32_t hw[4], lw[4];
    #pragma unroll
    for (int i = 0; i < 4; i++) {
        __nv_bfloat16 h1, h2;
        hw[i] = pack_hilo2(f[2*i], f[2*i+1], h1, h2);
        __nv_bfloat16 t1, t2;
        lw[i] = pack_hilo2(f[2*i]   - __bfloat162float(h1),
                           f[2*i+1] - __bfloat162float(h2), t1, t2);
    }
    hi = make_uint4(hw[0], hw[1], hw[2], hw[3]);
    lo = make_uint4(lw[0], lw[1], lw[2], lw[3]);
}
// swizzled byte offset within a tile region: rows of 128 bf16 (256B), 16B chunks
// chunk' = chunk ^ (row & 7)
__device__ __forceinline__ uint32_t swb(uint32_t regionB, int row, int col) {
    return regionB + (uint32_t)(row * 256) + (uint32_t)(((((col) >> 3) ^ (row & 7)) << 4));
}

// ---------------- RoPE table init ----------------
__global__ void init_tables_kernel()
{
    int t = blockIdx.x;
    int i = threadIdx.x;
    double freq = exp(-(double)i * (log(10000.0) / 64.0));
    float ang = (float)t * (float)freq;
    g_cos[t*64 + i] = (float)cos((double)ang);
    g_sin[t*64 + i] = (float)sin((double)ang);
}

// ---------------- fp32 -> (hi, lo) bf16 split (R4-proven) ----------------
__global__ void convert_hilo_kernel(const float* __restrict__ src, int which, int n4)
{
    int idx = blockIdx.x * blockDim.x + threadIdx.x;
    if (idx >= n4) return;
    const float* s = src ? src : g_ctx;
    __nv_bfloat16 *hi, *lo;
    switch (which) {
        case 1: hi = g_wqhi; lo = g_wqlo; break;
        case 2: hi = g_wkhi; lo = g_wklo; break;
        case 3: hi = g_wvhi; lo = g_wvlo; break;
        case 4: hi = g_wohi; lo = g_wolo; break;
        default: hi = g_xhi; lo = g_xlo; break;   // 0 and 5
    }
    float4 v = ((const float4*)s)[idx];
    uint4 h4, l4;
    split8(v, v, h4, l4);   // only first two words used below? no—use direct path
    __nv_bfloat16 h0 = __float2bfloat16(v.x);
    __nv_bfloat16 h1 = __float2bfloat16(v.y);
    __nv_bfloat16 h2 = __float2bfloat16(v.z);
    __nv_bfloat16 h3 = __float2bfloat16(v.w);
    __nv_bfloat16 l0 = __float2bfloat16(v.x - __bfloat162float(h0));
    __nv_bfloat16 l1 = __float2bfloat16(v.y - __bfloat162float(h1));
    __nv_bfloat16 l2 = __float2bfloat16(v.z - __bfloat162float(h2));
    __nv_bfloat16 l3 = __float2bfloat16(v.w - __bfloat162float(h3));
    __nv_bfloat162* hp = (__nv_bfloat162*)hi;
    __nv_bfloat162* lp = (__nv_bfloat162*)lo;
    hp[2*idx]   = __halves2bfloat162(h0, h1);
    hp[2*idx+1] = __halves2bfloat162(h2, h3);
    lp[2*idx]   = __halves2bfloat162(l0, l1);
    lp[2*idx+1] = __halves2bfloat162(l2, l3);
}

// ---------------- mma.sync bf16 hi/lo GEMM (R4-proven, unchanged) ----------------
#define KC 32
#define STR 40

__global__ void __launch_bounds__(256, 2) ms_gemm_kernel(float* __restrict__ Cp, int mode,
                                                         const int* __restrict__ tokpos)
{
    __shared__ __nv_bfloat16 sAh[128*STR];
    __shared__ __nv_bfloat16 sAl[128*STR];
    __shared__ __nv_bfloat16 sBh[128*STR];
    __shared__ __nv_bfloat16 sBl[128*STR];

    const int tid = threadIdx.x;
    const int wid = tid >> 5, lane = tid & 31;
    const int wm = wid >> 2, wn = wid & 3;
    const int bm = blockIdx.y * 128, bn = blockIdx.x * 128;

    const __nv_bfloat16 *Ah = g_xhi, *Al = g_xlo, *Bh, *Bl;
    if (mode == 0)      { Bh = g_wohi; Bl = g_wolo; }
    else if (mode == 1) { Bh = g_wqhi; Bl = g_wqlo; }
    else if (mode == 2) { Bh = g_wkhi; Bl = g_wklo; }
    else                { Bh = g_wvhi; Bl = g_wvlo; }

    float acc[4][4][4];
    #pragma unroll
    for (int i = 0; i < 4; i++)
        #pragma unroll
        for (int j = 0; j < 4; j++)
            #pragma unroll
            for (int d = 0; d < 4; d++) acc[i][j][d] = 0.f;

    const uint32_t sah = smem_u32(sAh), sal = smem_u32(sAl);
    const uint32_t sbh = smem_u32(sBh), sbl = smem_u32(sBl);
    const int r8 = lane & 7, sel = lane >> 3;
    const int a_row_part = wm*64 + r8 + (sel & 1) * 8;
    const int a_col_part = (sel >> 1) * 8;
    const int b_row_part = wn*32 + r8;
    const int b_col_part = (sel & 1) * 8;

    for (int c = 0; c < 64; c++) {
        const int k0 = c * KC;
        __syncthreads();
        #pragma unroll
        for (int t = 0; t < 2; t++) {
            const int slot = tid + t*256;
            const int row = slot >> 2, seg = slot & 3;
            const int so = row*STR + seg*8;
            const size_t ga = (size_t)(bm + row) * DMODEL + k0 + seg*8;
            const size_t gb = (size_t)(bn + row) * DMODEL + k0 + seg*8;
            *(uint4*)(sAh + so) = *(const uint4*)(Ah + ga);
            *(uint4*)(sAl + so) = *(const uint4*)(Al + ga);
            *(uint4*)(sBh + so) = *(const uint4*)(Bh + gb);
            *(uint4*)(sBl + so) = *(const uint4*)(Bl + gb);
        }
        __syncthreads();
        #pragma unroll
        for (int kk = 0; kk < 2; kk++) {
            const int kof = kk * 16;
            uint32_t bfh[4][2], bfl[4][2];
            #pragma unroll
            for (int an = 0; an < 4; an++) {
                const uint32_t ba = 2u * (uint32_t)((b_row_part + an*8)*STR + b_col_part + kof);
                ldsm_x2(bfh[an], sbh + ba);
                ldsm_x2(bfl[an], sbl + ba);
            }
            #pragma unroll
            for (int am = 0; am < 4; am++) {
                const uint32_t aa = 2u * (uint32_t)((a_row_part + am*16)*STR + a_col_part + kof);
                uint32_t afh[4], afl[4];
                ldsm_x4(afh, sah + aa);
                ldsm_x4(afl, sal + aa);
                #pragma unroll
                for (int an = 0; an < 4; an++) {
                    mma16816(acc[am][an], afh, bfh[an]);
                    mma16816(acc[am][an], afh, bfl[an]);
                    mma16816(acc[am][an], afl, bfh[an]);
                }
            }
        }
    }

    const int rr = lane >> 2;
    const int cc = (lane & 3) * 2;
    if (mode == 0) {
        #pragma unroll
        for (int am = 0; am < 4; am++)
            #pragma unroll
            for (int h2 = 0; h2 < 2; h2++) {
                const int m = bm + wm*64 + am*16 + rr + h2*8;
                #pragma unroll
                for (int an = 0; an < 4; an++) {
                    const int n = bn + wn*32 + an*8 + cc;
                    *(float2*)(Cp + (size_t)m * DMODEL + n) =
                        make_float2(acc[am][an][h2*2], acc[am][an][h2*2+1]);
                }
            }
    } else {
        const int h = bn >> 7;
        float* base = (mode == 1) ? g_Q : ((mode == 2) ? g_K : g_V);
        const float qscale = 0.08838834764831845f;  // 1/sqrt(128)
        #pragma unroll
        for (int am = 0; am < 4; am++)
            #pragma unroll
            for (int h2 = 0; h2 < 2; h2++) {
                const int m = bm + wm*64 + am*16 + rr + h2*8;
                const int b = m >> 11;
                const int s = m & (SEQL - 1);
                float* drow = base + ((size_t)(b * NHEADS + h) * SEQL + s) * DKH;
                if (mode == 3) {
                    #pragma unroll
                    for (int an = 0; an < 4; an++) {
                        const int d = wn*32 + an*8 + cc;
                        *(float2*)(drow + d) =
                            make_float2(acc[am][an][h2*2], acc[am][an][h2*2+1]);
                    }
                } else {
                    const int p = tokpos[s];
                    #pragma unroll
                    for (int an = 0; an < 4; an++) {
                        const int d = wn*32 + an*8 + cc;
                        const int pi = d >> 1;
                        const float co = g_cos[p*64 + pi];
                        const float si = g_sin[p*64 + pi];
                        const float x1 = acc[am][an][h2*2];
                        const float x2 = acc[am][an][h2*2+1];
                        float r1 = co*x1 - si*x2;
                        float r2 = si*x1 + co*x2;
                        if (mode == 1) { r1 *= qscale; r2 *= qscale; }
                        *(float2*)(drow + d) = make_float2(r1, r2);
                    }
                }
            }
    }
}

// ---------------- flash attention via mma.sync bf16 hi/lo (96KB smem) ----------------
// CTA = 128 q-rows, 8 warps x 16 rows, k-tiles of 32. Reads fp32 QKV, converts
// hi/lo while staging (swizzled smem, stride 128). Writes fp32 g_ctx.
// regions (byte offsets): QH 0, QL 32768, KH 65536, KL 73728, VH 81920, VL 90112
#define QH_B 0u
#define QL_B 32768u
#define KH_B 65536u
#define KL_B 73728u
#define VH_B 81920u
#define VL_B 90112u
#define ASM_BYTES 98304

__global__ void __launch_bounds__(256) mha_mma_kernel()
{
    extern __shared__ char sbc[];
    const uint32_t sbase = smem_u32(sbc);
    const int tid = threadIdx.x, wid = tid >> 5, lane = tid & 31;
    const int qi = (int)gridDim.x - 1 - (int)blockIdx.x;   // big q-tiles first
    const int bh = blockIdx.y;
    const int q0 = qi * 128;
    const size_t boff = (size_t)bh * SEQL * DKH;
    const float* Qb = g_Q + boff;
    const float* Kb = g_K + boff;
    const float* Vb = g_V + boff;

    // stage Q (fp32 -> hi/lo, swizzled)
    for (int idx = tid; idx < 128*16; idx += 256) {
        const int row = idx >> 4, chunk = idx & 15;
        const float* src = Qb + (size_t)(q0 + row) * DKH + chunk * 8;
        float4 a = *(const float4*)src;
        float4 b = *(const float4*)(src + 4);
        uint4 hi, lo;
        split8(a, b, hi, lo);
        const uint32_t off = (uint32_t)(row * 256) + (uint32_t)(((chunk ^ (row & 7)) << 4));
        *(uint4*)(sbc + QH_B + off) = hi;
        *(uint4*)(sbc + QL_B + off) = lo;
    }

    const int r8 = lane & 7, sel = lane >> 3;
    const int qrow = wid*16 + r8 + ((sel & 1) << 3);
    const int qcolb = (sel >> 1) << 3;
    const int krow_b = r8 + ((sel >> 1) << 3);
    const int kcolb = (sel & 1) << 3;
    const int vrow_b = r8 + ((sel & 1) << 3);
    const int vcolb = (sel >> 1) << 3;

    const int rr = lane >> 2, cc2 = (lane & 3) * 2;
    const int rw0 = q0 + wid * 16;
    float m0 = -INFINITY, m1 = -INFINITY, l0 = 0.f, l1 = 0.f;
    float oacc[16][4];
    #pragma unroll
    for (int i = 0; i < 16; i++)
        #pragma unroll
        for (int j = 0; j < 4; j++) oacc[i][j] = 0.f;

    const int nkt = 4 * qi + 4;
    for (int kt = 0; kt < nkt; kt++) {
        const int k0g = kt * 32;
        __syncthreads();
        // stage K,V tile (32 rows each, fp32 -> hi/lo, swizzled)
        for (int idx = tid; idx < 1024; idx += 256) {
            const int which = idx >> 9;            // 0: K, 1: V
            const int rem = idx & 511;
            const int row = rem >> 4, chunk = rem & 15;
            const float* src = (which ? Vb : Kb) + (size_t)(k0g + row) * DKH + chunk * 8;
            float4 a = *(const float4*)src;
            float4 b = *(const float4*)(src + 4);
            uint4 hi, lo;
            split8(a, b, hi, lo);
            const uint32_t off = (uint32_t)(row * 256) + (uint32_t)(((chunk ^ (row & 7)) << 4));
            const uint32_t hB = which ? VH_B : KH_B;
            const uint32_t lB = which ? VL_B : KL_B;
            *(uint4*)(sbc + hB + off) = hi;
            *(uint4*)(sbc + lB + off) = lo;
        }
        __syncthreads();

        if (k0g <= rw0 + 15) {                 // warp-tile not fully masked
            // ---- S = Q K^T (hi/lo 3 passes), S is 16x32 per warp ----
            float sacc[4][4];
            #pragma unroll
            for (int j = 0; j < 4; j++)
                #pragma unroll
                for (int d = 0; d < 4; d++) sacc[j][d] = 0.f;
            #pragma unroll
            for (int kk = 0; kk < 8; kk++) {
                uint32_t afh[4], afl[4];
                ldsm_x4(afh, sbase + swb(QH_B, qrow, qcolb + kk*16));
                ldsm_x4(afl, sbase + swb(QL_B, qrow, qcolb + kk*16));
                #pragma unroll
                for (int np = 0; np < 2; np++) {
                    uint32_t bh4[4], bl4[4];
                    ldsm_x4(bh4, sbase + swb(KH_B, krow_b + np*16, kcolb + kk*16));
                    ldsm_x4(bl4, sbase + swb(KL_B, krow_b + np*16, kcolb + kk*16));
                    mma16816(sacc[2*np],   afh, bh4);
                    mma16816(sacc[2*np],   afh, bl4);
                    mma16816(sacc[2*np],   afl, bh4);
                    mma16816(sacc[2*np+1], afh, bh4+2);
                    mma16816(sacc[2*np+1], afh, bl4+2);
                    mma16816(sacc[2*np+1], afl, bh4+2);
                }
            }
            // ---- causal mask ----
            if (k0g + 31 > rw0) {
                const int row0 = rw0 + rr, row1 = row0 + 8;
                #pragma unroll
                for (int j = 0; j < 4; j++) {
                    const int c0 = k0g + j*8 + cc2;
                    if (c0     > row0) sacc[j][0] = -1e30f;
                    if (c0 + 1 > row0) sacc[j][1] = -1e30f;
                    if (c0     > row1) sacc[j][2] = -1e30f;
                    if (c0 + 1 > row1) sacc[j][3] = -1e30f;
                }
            }
            // ---- online softmax ----
            float mt0 = -INFINITY, mt1 = -INFINITY;
            #pragma unroll
            for (int j = 0; j < 4; j++) {
                mt0 = fmaxf(mt0, fmaxf(sacc[j][0], sacc[j][1]));
                mt1 = fmaxf(mt1, fmaxf(sacc[j][2], sacc[j][3]));
            }
            mt0 = fmaxf(mt0, __shfl_xor_sync(0xffffffffu, mt0, 1));
            mt0 = fmaxf(mt0, __shfl_xor_sync(0xffffffffu, mt0, 2));
            mt1 = fmaxf(mt1, __shfl_xor_sync(0xffffffffu, mt1, 1));
            mt1 = fmaxf(mt1, __shfl_xor_sync(0xffffffffu, mt1, 2));
            const float mn0 = fmaxf(m0, mt0), mn1 = fmaxf(m1, mt1);
            const float al0 = __expf(m0 - mn0), al1 = __expf(m1 - mn1);
            m0 = mn0; m1 = mn1;
            float s0 = 0.f, s1 = 0.f;
            uint32_t pah[2][4], pal[2][4];
            #pragma unroll
            for (int j = 0; j < 4; j++) {
                const float p00 = __expf(sacc[j][0] - m0);
                const float p01 = __expf(sacc[j][1] - m0);
                const float p10 = __expf(sacc[j][2] - m1);
                const float p11 = __expf(sacc[j][3] - m1);
                s0 += p00 + p01; s1 += p10 + p11;
                __nv_bfloat16 h00, h01, h10, h11;
                const uint32_t ph0 = pack_hilo2(p00, p01, h00, h01);
                const uint32_t ph1 = pack_hilo2(p10, p11, h10, h11);
                __nv_bfloat16 tt0, tt1;
                const uint32_t pl0 = pack_hilo2(p00 - __bfloat162float(h00),
                                                p01 - __bfloat162float(h01), tt0, tt1);
                const uint32_t pl1 = pack_hilo2(p10 - __bfloat162float(h10),
                                                p11 - __bfloat162float(h11), tt0, tt1);
                const int t = j >> 1, u = (j & 1) * 2;
                pah[t][u]   = ph0; pah[t][u+1] = ph1;
                pal[t][u]   = pl0; pal[t][u+1] = pl1;
            }
            s0 += __shfl_xor_sync(0xffffffffu, s0, 1);
            s0 += __shfl_xor_sync(0xffffffffu, s0, 2);
            s1 += __shfl_xor_sync(0xffffffffu, s1, 1);
            s1 += __shfl_xor_sync(0xffffffffu, s1, 2);
            l0 = l0*al0 + s0; l1 = l1*al1 + s1;
            #pragma unroll
            for (int na = 0; na < 16; na++) {
                oacc[na][0] *= al0; oacc[na][1] *= al0;
                oacc[na][2] *= al1; oacc[na][3] *= al1;
            }
            // ---- O += P V (hi/lo 3 passes, V via ldmatrix.trans) ----
            #pragma unroll
            for (int t = 0; t < 2; t++) {
                #pragma unroll
                for (int np = 0; np < 8; np++) {
                    uint32_t vh4[4], vl4[4];
                    ldsm_x4_t(vh4, sbase + swb(VH_B, vrow_b + t*16, vcolb + np*16));
                    ldsm_x4_t(vl4, sbase + swb(VL_B, vrow_b + t*16, vcolb + np*16));
                    mma16816(oacc[2*np],   pah[t], vh4);
                    mma16816(oacc[2*np],   pah[t], vl4);
                    mma16816(oacc[2*np],   pal[t], vh4);
                    mma16816(oacc[2*np+1], pah[t], vh4+2);
                    mma16816(oacc[2*np+1], pah[t], vl4+2);
                    mma16816(oacc[2*np+1], pal[t], vh4+2);
                }
            }
        }
    }

    // ---- epilogue: fp32 ctx (R4-compatible pipeline) ----
    const float inv0 = 1.f / l0, inv1 = 1.f / l1;
    const int brow = bh >> 4, hh = bh & 15;
    const int s0r = rw0 + rr, s1r = s0r + 8;
    float* d0 = g_ctx + ((size_t)(brow*SEQL + s0r))*DMODEL + hh*DKH + cc2;
    float* d1 = g_ctx + ((size_t)(brow*SEQL + s1r))*DMODEL + hh*DKH + cc2;
    #pragma unroll
    for (int na = 0; na < 16; na++) {
        *(float2*)(d0 + na*8) = make_float2(oacc[na][0]*inv0, oacc[na][1]*inv0);
        *(float2*)(d1 + na*8) = make_float2(oacc[na][2]*inv1, oacc[na][3]*inv1);
    }
}

// ---------------- launch ----------------
extern "C" void kernel_launch(void* const* d_in, const int* in_sizes, int n_in,
                              void* d_out, int out_size)
{
    (void)in_sizes; (void)n_in; (void)out_size;
    const float* x      = (const float*)d_in[0];
    const int*   tokpos = (const int*)d_in[1];
    const float* Wq     = (const float*)d_in[2];
    const float* Wk     = (const float*)d_in[3];
    const float* Wv     = (const float*)d_in[4];
    const float* Wo     = (const float*)d_in[5];
    float* out = (float*)d_out;

    init_tables_kernel<<<SEQL, 64>>>();

    const int n4x = MROWS * DMODEL / 4;
    const int n4w = DMODEL * DMODEL / 4;
    convert_hilo_kernel<<<n4x/256, 256>>>(x,  0, n4x);
    convert_hilo_kernel<<<n4w/256, 256>>>(Wq, 1, n4w);
    convert_hilo_kernel<<<n4w/256, 256>>>(Wk, 2, n4w);
    convert_hilo_kernel<<<n4w/256, 256>>>(Wv, 3, n4w);
    convert_hilo_kernel<<<n4w/256, 256>>>(Wo, 4, n4w);

    dim3 gg(DMODEL / 128, MROWS / 128);
    ms_gemm_kernel<<<gg, 256>>>(nullptr, 1, tokpos);   // Q (+RoPE, +scale) -> g_Q fp32
    ms_gemm_kernel<<<gg, 256>>>(nullptr, 2, tokpos);   // K (+RoPE)         -> g_K
    ms_gemm_kernel<<<gg, 256>>>(nullptr, 3, tokpos);   // V                 -> g_V

    cudaFuncSetAttribute(mha_mma_kernel, cudaFuncAttributeMaxDynamicSharedMemorySize, ASM_BYTES);
    mha_mma_kernel<<<dim3(SEQL/128, BATCH*NHEADS), 256, ASM_BYTES>>>();

    convert_hilo_kernel<<<n4x/256, 256>>>(nullptr, 5, n4x);  // ctx -> xhi/xlo
    ms_gemm_kernel<<<gg, 256>>>(out, 0, nullptr);            // output projection
}